// round 7
// baseline (speedup 1.0000x reference)
#include <cuda_runtime.h>
#include <cuda_fp16.h>
#include <cstdint>

// Tropical (max-plus) matmul: Y[b, j] = max_i (X[b, i] + W[j, i])
// fp16 path with per-row fp32 shift:
//   M_b = max_i X[b,i];  Xh = half(X - M_b);  Wh = half(W)
//   Y' = max-plus in packed fp16 (HADD2/HMNMX2 paired over k);  Y = Y' + M_b.
// Measured rel_err ~1.3e-6 (winners near 0; max accumulation exact).
//
// R7: single-buffered smem (23KB -> 8 blocks/SM resident, 32 warps/SM) so
// per-chunk cp.async waits are hidden by peer blocks and issue efficiency
// rises; MLP=4 W-prep; finer combine launch.

#define B_DIM   512
#define IN_DIM  1024
#define OUT_DIM 1024

#define SPLITK  8
#define KSEG    (IN_DIM / SPLITK)   // 128
#define BKH     64                  // halves per chunk
#define NCHH    (KSEG / BKH)        // 2
#define BMH     32
#define BNH     128
#define PADK    72                  // padded halves per smem row
#define NT      128

__device__ __half Xh[B_DIM * IN_DIM];
__device__ __half Wh[OUT_DIM * IN_DIM];
__device__ float  Mrow[B_DIM];
__device__ __half g_parth[SPLITK][B_DIM * OUT_DIM];   // 8 MB

#define CPA16(dst_u32, src_ptr) \
    asm volatile("cp.async.cg.shared.global [%0], [%1], 16;" \
                 :: "r"(dst_u32), "l"(src_ptr))
#define CPA_COMMIT() asm volatile("cp.async.commit_group;")
#define CPA_WAIT0()  asm volatile("cp.async.wait_group 0;")

// ---------- fused prep: blocks [0,512) shift+cvt X; [512,768) cvt W, MLP=4 ----------
__global__ __launch_bounds__(256)
void prep_xw(const float* __restrict__ X, const float* __restrict__ W) {
    const int t = threadIdx.x;
    if (blockIdx.x < B_DIM) {
        __shared__ float wmax[8];
        const int b = blockIdx.x;
        float4 v = ((const float4*)(X + (size_t)b * IN_DIM))[t];
        float m = fmaxf(fmaxf(v.x, v.y), fmaxf(v.z, v.w));
#pragma unroll
        for (int o = 16; o; o >>= 1) m = fmaxf(m, __shfl_xor_sync(~0u, m, o));
        if ((t & 31) == 0) wmax[t >> 5] = m;
        __syncthreads();
        const float M = fmaxf(fmaxf(fmaxf(wmax[0], wmax[1]), fmaxf(wmax[2], wmax[3])),
                              fmaxf(fmaxf(wmax[4], wmax[5]), fmaxf(wmax[6], wmax[7])));
        if (t == 0) Mrow[b] = M;
        __half2* dst = (__half2*)(Xh + (size_t)b * IN_DIM);
        dst[2 * t]     = __floats2half2_rn(v.x - M, v.y - M);
        dst[2 * t + 1] = __floats2half2_rn(v.z - M, v.w - M);
    } else {
        // W: 262144 float4s over 256 blocks x 256 threads x 4 independent loads
        const int base = (blockIdx.x - B_DIM) * 1024 + t;
        float4 v0 = ((const float4*)W)[base];
        float4 v1 = ((const float4*)W)[base + 256];
        float4 v2 = ((const float4*)W)[base + 512];
        float4 v3 = ((const float4*)W)[base + 768];
        __half2* dst = (__half2*)Wh;
        dst[2 * (base)       ] = __floats2half2_rn(v0.x, v0.y);
        dst[2 * (base)    + 1] = __floats2half2_rn(v0.z, v0.w);
        dst[2 * (base + 256)    ] = __floats2half2_rn(v1.x, v1.y);
        dst[2 * (base + 256) + 1] = __floats2half2_rn(v1.z, v1.w);
        dst[2 * (base + 512)    ] = __floats2half2_rn(v2.x, v2.y);
        dst[2 * (base + 512) + 1] = __floats2half2_rn(v2.z, v2.w);
        dst[2 * (base + 768)    ] = __floats2half2_rn(v3.x, v3.y);
        dst[2 * (base + 768) + 1] = __floats2half2_rn(v3.z, v3.w);
    }
}

// ---------- main: fp16 split-K max-plus, single-buffered ----------
__global__ __launch_bounds__(NT, 8)
void tropical_h() {
    __shared__ __half xs[BMH][PADK];   //  4.6 KB
    __shared__ __half ws[BNH][PADK];   // 18.4 KB

    const int t = threadIdx.x, lane = t & 31, wid = t >> 5;
    const int colg = (lane & 7) | ((wid & 1) << 3);    // 0..15
    const int rowg = (lane >> 3) | ((wid >> 1) << 2);  // 0..7
    const int brow = blockIdx.y * BMH;
    const int bcol = blockIdx.x * BNH;
    const int kz   = blockIdx.z;

    // staging map: 4 consecutive lanes cover 64B of one tensor row
    const int r = t >> 2;   // 0..31
    const int q = t & 3;    // 16B-quad
    const __half* Xsrc = Xh + (size_t)(brow + r) * IN_DIM + kz * KSEG + q * 8;
    const __half* Wsrc = Wh + (size_t)(bcol + r) * IN_DIM + kz * KSEG + q * 8;

    const unsigned xd = (unsigned)__cvta_generic_to_shared(&xs[0][0])
                        + (unsigned)(r * PADK + q * 8) * 2;
    const unsigned wd = (unsigned)__cvta_generic_to_shared(&ws[0][0])
                        + (unsigned)(r * PADK + q * 8) * 2;
    const unsigned WROW32 = (unsigned)(32 * PADK) * 2;

#define STAGE(c) do {                                                        \
        const __half* xsp = Xsrc + (c) * BKH;                                \
        const __half* wsp = Wsrc + (c) * BKH;                                \
        CPA16(xd,      xsp);                                                 \
        CPA16(xd + 64, xsp + 32);                                            \
        _Pragma("unroll")                                                    \
        for (int p = 0; p < 4; ++p) {                                        \
            CPA16(wd + p * WROW32,      wsp + (size_t)32 * p * IN_DIM);      \
            CPA16(wd + p * WROW32 + 64, wsp + (size_t)32 * p * IN_DIM + 32); \
        }                                                                    \
        CPA_COMMIT();                                                        \
    } while (0)

    __half2 acc[4][8];
    const __half2 ninf = __floats2half2_rn(-60000.f, -60000.f);
#pragma unroll
    for (int i = 0; i < 4; ++i)
#pragma unroll
        for (int c = 0; c < 8; ++c)
            acc[i][c] = ninf;

#pragma unroll 1
    for (int c = 0; c < NCHH; ++c) {
        if (c > 0) __syncthreads();   // everyone done reading before restage
        STAGE(c);
        CPA_WAIT0();
        __syncthreads();

#pragma unroll 2
        for (int m = 0; m < 8; ++m) {
            uint4 xv[4], wv[8];
#pragma unroll
            for (int i = 0; i < 4; ++i)
                xv[i] = *(const uint4*)(&xs[0][0] + (rowg + 8 * i) * PADK + 8 * m);
#pragma unroll
            for (int j = 0; j < 8; ++j)
                wv[j] = *(const uint4*)(&ws[0][0] + (colg + 16 * j) * PADK + 8 * m);

            const __half2* x2 = (const __half2*)xv;   // [i*4 + p]
            const __half2* w2 = (const __half2*)wv;   // [j*4 + p]
#pragma unroll
            for (int i = 0; i < 4; ++i)
#pragma unroll
                for (int j = 0; j < 8; ++j)
#pragma unroll
                    for (int p = 0; p < 4; ++p)
                        acc[i][j] = __hmax2(acc[i][j],
                                            __hadd2(x2[i * 4 + p], w2[j * 4 + p]));
        }
    }

    // epilogue: pair-reduce, write half partials
    __half* out = &g_parth[kz][0];
#pragma unroll
    for (int i = 0; i < 4; ++i)
#pragma unroll
        for (int j = 0; j < 8; ++j) {
            const __half2 a = acc[i][j];
            out[(size_t)(brow + rowg + 8 * i) * OUT_DIM + bcol + colg + 16 * j] =
                __hmax(__low2half(a), __high2half(a));
        }
#undef STAGE
}

// ---------- combine: 8-way packed max + add back row shift ----------
__global__ __launch_bounds__(128)
void combine_max8(float* __restrict__ Y) {
    const int i = blockIdx.x * 128 + threadIdx.x;   // 8-half chunk index
    const float M = Mrow[(i << 3) >> 10];           // 8 halves stay in one row
    uint4 v = ((const uint4*)g_parth[0])[i];
    __half2 m0 = ((const __half2*)&v)[0], m1 = ((const __half2*)&v)[1];
    __half2 m2 = ((const __half2*)&v)[2], m3 = ((const __half2*)&v)[3];
#pragma unroll
    for (int s = 1; s < SPLITK; ++s) {
        uint4 u = ((const uint4*)g_parth[s])[i];
        m0 = __hmax2(m0, ((const __half2*)&u)[0]);
        m1 = __hmax2(m1, ((const __half2*)&u)[1]);
        m2 = __hmax2(m2, ((const __half2*)&u)[2]);
        m3 = __hmax2(m3, ((const __half2*)&u)[3]);
    }
    float4* Yo = (float4*)(Y + ((size_t)i << 3));
    float2 f0 = __half22float2(m0), f1 = __half22float2(m1);
    float2 f2 = __half22float2(m2), f3 = __half22float2(m3);
    Yo[0] = make_float4(f0.x + M, f0.y + M, f1.x + M, f1.y + M);
    Yo[1] = make_float4(f2.x + M, f2.y + M, f3.x + M, f3.y + M);
}

extern "C" void kernel_launch(void* const* d_in, const int* in_sizes, int n_in,
                              void* d_out, int out_size) {
    const float* X = (const float*)d_in[0];   // [512, 1024]
    const float* W = (const float*)d_in[1];   // [1024, 1024]
    float* Y = (float*)d_out;                 // [512, 1024]
    (void)in_sizes; (void)n_in; (void)out_size;

    prep_xw<<<B_DIM + 256, 256>>>(X, W);             // 768 blocks

    dim3 grid(OUT_DIM / BNH, B_DIM / BMH, SPLITK);   // (8, 16, 8) = 1024 blocks
    tropical_h<<<grid, NT>>>();

    combine_max8<<<B_DIM * OUT_DIM / 8 / 128, 128>>>(Y);   // 512 blocks
}

// round 9
// speedup vs baseline: 1.8389x; 1.8389x over previous
#include <cuda_runtime.h>
#include <cuda_fp16.h>
#include <cstdint>

// Tropical (max-plus) matmul: Y[b, j] = max_i (X[b, i] + W[j, i])
// fp16 path with per-row fp32 shift:
//   M_b = max_i X[b,i];  Xh = half(X - M_b);  Wh = half(W)
//   Y' = max-plus in packed fp16 (HADD2/HMNMX2 paired over k);  Y = Y' + M_b.
// Measured rel_err ~1.3e-6.
//
// R9: same as R8 intent (R6 double-buffered main kernel; W-prep with
// unit-stride MLP=2 loads + packed 16B stores), with the fake
// __half2_as_ushort2 intrinsic replaced by plain reinterpretation.

#define B_DIM   512
#define IN_DIM  1024
#define OUT_DIM 1024

#define SPLITK  8
#define KSEG    (IN_DIM / SPLITK)   // 128
#define BKH     64                  // halves per chunk
#define NCHH    (KSEG / BKH)        // 2
#define BMH     32
#define BNH     128
#define PADK    72                  // padded halves per smem row
#define NT      128

__device__ __half Xh[B_DIM * IN_DIM];
__device__ __half Wh[OUT_DIM * IN_DIM];
__device__ float  Mrow[B_DIM];
__device__ __half g_parth[SPLITK][B_DIM * OUT_DIM];   // 8 MB

#define CPA16(dst_u32, src_ptr) \
    asm volatile("cp.async.cg.shared.global [%0], [%1], 16;" \
                 :: "r"(dst_u32), "l"(src_ptr))
#define CPA_COMMIT() asm volatile("cp.async.commit_group;")
#define CPA_WAIT1()  asm volatile("cp.async.wait_group 1;")
#define CPA_WAIT0()  asm volatile("cp.async.wait_group 0;")

// ---------- fused prep: blocks [0,512) shift+cvt X; [512,1024) cvt W ----------
__global__ __launch_bounds__(256)
void prep_xw(const float* __restrict__ X, const float* __restrict__ W) {
    const int t = threadIdx.x;
    if (blockIdx.x < B_DIM) {
        __shared__ float wmax[8];
        const int b = blockIdx.x;
        float4 v = ((const float4*)(X + (size_t)b * IN_DIM))[t];
        float m = fmaxf(fmaxf(v.x, v.y), fmaxf(v.z, v.w));
#pragma unroll
        for (int o = 16; o; o >>= 1) m = fmaxf(m, __shfl_xor_sync(~0u, m, o));
        if ((t & 31) == 0) wmax[t >> 5] = m;
        __syncthreads();
        const float M = fmaxf(fmaxf(fmaxf(wmax[0], wmax[1]), fmaxf(wmax[2], wmax[3])),
                              fmaxf(fmaxf(wmax[4], wmax[5]), fmaxf(wmax[6], wmax[7])));
        if (t == 0) Mrow[b] = M;
        __half2* dst = (__half2*)(Xh + (size_t)b * IN_DIM);
        dst[2 * t]     = __floats2half2_rn(v.x - M, v.y - M);
        dst[2 * t + 1] = __floats2half2_rn(v.z - M, v.w - M);
    } else {
        // W: 262144 float4s over 512 blocks; unit-stride MLP=2, 8B packed stores
        const int base = (blockIdx.x - B_DIM) * 512 + t;   // float4 index
        float4 v0 = ((const float4*)W)[base];
        float4 v1 = ((const float4*)W)[base + 256];
        __half2 a0 = __floats2half2_rn(v0.x, v0.y);
        __half2 a1 = __floats2half2_rn(v0.z, v0.w);
        __half2 b0 = __floats2half2_rn(v1.x, v1.y);
        __half2 b1 = __floats2half2_rn(v1.z, v1.w);
        uint2* dst = (uint2*)Wh;   // 8 halves per float4 = one uint2
        uint2 p0, p1;
        p0.x = *(const unsigned*)&a0;  p0.y = *(const unsigned*)&a1;
        p1.x = *(const unsigned*)&b0;  p1.y = *(const unsigned*)&b1;
        dst[base]       = p0;
        dst[base + 256] = p1;
    }
}

// ---------- main: fp16 split-K max-plus (R6 double-buffered version) ----------
__global__ __launch_bounds__(NT)
void tropical_h() {
    __shared__ __half xs[2][BMH][PADK];   //  9.2 KB
    __shared__ __half ws[2][BNH][PADK];   // 36.9 KB

    const int t = threadIdx.x, lane = t & 31, wid = t >> 5;
    const int colg = (lane & 7) | ((wid & 1) << 3);    // 0..15
    const int rowg = (lane >> 3) | ((wid >> 1) << 2);  // 0..7
    const int brow = blockIdx.y * BMH;
    const int bcol = blockIdx.x * BNH;
    const int kz   = blockIdx.z;

    const int r = t >> 2;   // 0..31
    const int q = t & 3;    // 16B-quad
    const __half* Xsrc = Xh + (size_t)(brow + r) * IN_DIM + kz * KSEG + q * 8;
    const __half* Wsrc = Wh + (size_t)(bcol + r) * IN_DIM + kz * KSEG + q * 8;

    const unsigned xs_base = (unsigned)__cvta_generic_to_shared(&xs[0][0][0]);
    const unsigned ws_base = (unsigned)__cvta_generic_to_shared(&ws[0][0][0]);
    const unsigned xd = xs_base + (unsigned)(r * PADK + q * 8) * 2;
    const unsigned wd = ws_base + (unsigned)(r * PADK + q * 8) * 2;
    const unsigned XBUF   = (unsigned)(BMH * PADK) * 2;
    const unsigned WBUF   = (unsigned)(BNH * PADK) * 2;
    const unsigned WROW32 = (unsigned)(32 * PADK) * 2;

#define STAGE(c, buf) do {                                                   \
        const __half* xsp = Xsrc + (c) * BKH;                                \
        const __half* wsp = Wsrc + (c) * BKH;                                \
        CPA16(xd + (buf) * XBUF,      xsp);                                  \
        CPA16(xd + (buf) * XBUF + 64, xsp + 32);                             \
        _Pragma("unroll")                                                    \
        for (int p = 0; p < 4; ++p) {                                        \
            CPA16(wd + (buf) * WBUF + p * WROW32,      wsp + (size_t)32 * p * IN_DIM); \
            CPA16(wd + (buf) * WBUF + p * WROW32 + 64, wsp + (size_t)32 * p * IN_DIM + 32); \
        }                                                                    \
        CPA_COMMIT();                                                        \
    } while (0)

    __half2 acc[4][8];
    const __half2 ninf = __floats2half2_rn(-60000.f, -60000.f);
#pragma unroll
    for (int i = 0; i < 4; ++i)
#pragma unroll
        for (int c = 0; c < 8; ++c)
            acc[i][c] = ninf;

    STAGE(0, 0);

#pragma unroll 1
    for (int c = 0; c < NCHH; ++c) {
        if (c + 1 < NCHH) { STAGE(c + 1, (c + 1) & 1); CPA_WAIT1(); }
        else              { CPA_WAIT0(); }
        __syncthreads();

        const int buf = c & 1;
        const __half* xb = &xs[buf][0][0];
        const __half* wb = &ws[buf][0][0];

#pragma unroll 2
        for (int m = 0; m < 8; ++m) {
            uint4 xv[4], wv[8];
#pragma unroll
            for (int i = 0; i < 4; ++i)
                xv[i] = *(const uint4*)(xb + (rowg + 8 * i) * PADK + 8 * m);
#pragma unroll
            for (int j = 0; j < 8; ++j)
                wv[j] = *(const uint4*)(wb + (colg + 16 * j) * PADK + 8 * m);

            const __half2* x2 = (const __half2*)xv;   // [i*4 + p]
            const __half2* w2 = (const __half2*)wv;   // [j*4 + p]
#pragma unroll
            for (int i = 0; i < 4; ++i)
#pragma unroll
                for (int j = 0; j < 8; ++j)
#pragma unroll
                    for (int p = 0; p < 4; ++p)
                        acc[i][j] = __hmax2(acc[i][j],
                                            __hadd2(x2[i * 4 + p], w2[j * 4 + p]));
        }

        if (c + 1 < NCHH) __syncthreads();   // protect buf before restage
    }

    // epilogue: pair-reduce, write half partials
    __half* out = &g_parth[kz][0];
#pragma unroll
    for (int i = 0; i < 4; ++i)
#pragma unroll
        for (int j = 0; j < 8; ++j) {
            const __half2 a = acc[i][j];
            out[(size_t)(brow + rowg + 8 * i) * OUT_DIM + bcol + colg + 16 * j] =
                __hmax(__low2half(a), __high2half(a));
        }
#undef STAGE
}

// ---------- combine: 8-way packed max + add back row shift ----------
__global__ __launch_bounds__(256)
void combine_max8(float* __restrict__ Y) {
    const int i = blockIdx.x * 256 + threadIdx.x;   // 8-half chunk index
    const float M = Mrow[(i << 3) >> 10];           // 8 halves stay in one row
    uint4 v = ((const uint4*)g_parth[0])[i];
    __half2 m0 = ((const __half2*)&v)[0], m1 = ((const __half2*)&v)[1];
    __half2 m2 = ((const __half2*)&v)[2], m3 = ((const __half2*)&v)[3];
#pragma unroll
    for (int s = 1; s < SPLITK; ++s) {
        uint4 u = ((const uint4*)g_parth[s])[i];
        m0 = __hmax2(m0, ((const __half2*)&u)[0]);
        m1 = __hmax2(m1, ((const __half2*)&u)[1]);
        m2 = __hmax2(m2, ((const __half2*)&u)[2]);
        m3 = __hmax2(m3, ((const __half2*)&u)[3]);
    }
    float4* Yo = (float4*)(Y + ((size_t)i << 3));
    float2 f0 = __half22float2(m0), f1 = __half22float2(m1);
    float2 f2 = __half22float2(m2), f3 = __half22float2(m3);
    Yo[0] = make_float4(f0.x + M, f0.y + M, f1.x + M, f1.y + M);
    Yo[1] = make_float4(f2.x + M, f2.y + M, f3.x + M, f3.y + M);
}

extern "C" void kernel_launch(void* const* d_in, const int* in_sizes, int n_in,
                              void* d_out, int out_size) {
    const float* X = (const float*)d_in[0];   // [512, 1024]
    const float* W = (const float*)d_in[1];   // [1024, 1024]
    float* Y = (float*)d_out;                 // [512, 1024]
    (void)in_sizes; (void)n_in; (void)out_size;

    prep_xw<<<B_DIM + 512, 256>>>(X, W);             // 1024 blocks

    dim3 grid(OUT_DIM / BNH, B_DIM / BMH, SPLITK);   // (8, 16, 8) = 1024 blocks
    tropical_h<<<grid, NT>>>();

    combine_max8<<<B_DIM * OUT_DIM / 8 / 256, 256>>>(Y);   // 256 blocks
}